// round 4
// baseline (speedup 1.0000x reference)
#include <cuda_runtime.h>

// Residual VQ (L=8, G=2, K=1024, D=256), B=16, T=4096, N=B*T=65536.
// Bit-replicates CPU-JAX (XLA/Eigen) fp32 semantics; GEMM uses packed
// fma.rn.f32x2 (2 independent rn-rounded fp32 FMA lanes -> bit-identical
// per-chain results at 2x throughput).
// Outputs: [0,33554432) qout [B,C,T]; [33554432] loss; [+1,+1048576) indices [L,G,N]

#define LL 8
#define GG 2
#define KK 1024
#define DD 256
#define TT 4096
#define NTOK 65536ull
#define TILE 64
#define NTH 256
#define EPITCH 132

#define QOUT_ELEMS 33554432ull
#define LOSS_OFF   33554432ull
#define IDX_OFF    33554433ull

__device__ float  g_e2[LL * GG * KK];
__device__ double g_loss[2048];

typedef unsigned long long u64t;

__device__ __forceinline__ u64t dup2(float v) {
    u64t r;
    asm("mov.b64 %0, {%1, %1};" : "=l"(r) : "f"(v));
    return r;
}
__device__ __forceinline__ void fma2(u64t& d, u64t a, u64t b) {
    asm("fma.rn.f32x2 %0, %1, %2, %3;" : "=l"(d) : "l"(a), "l"(b), "l"(d));
}
__device__ __forceinline__ void unpack2(u64t v, float& lo, float& hi) {
    asm("mov.b64 {%0, %1}, %2;" : "=f"(lo), "=f"(hi) : "l"(v));
}

// ---------------------------------------------------------------- ||e||^2 (exact ref rounding)
__global__ void e2_kernel(const float* __restrict__ cb) {
    int c = blockIdx.x * blockDim.x + threadIdx.x;
    if (c >= LL * GG * KK) return;
    const float* e = cb + (size_t)c * DD;
    float s = 0.0f;
    for (int d = 0; d < DD; ++d) {
        float v = e[d];
        s = __fadd_rn(s, __fmul_rn(v, v));
    }
    g_e2[c] = s;
}

// ---------------------------------------------------------------- main
__global__ void __launch_bounds__(NTH, 2)
rvq_kernel(const float* __restrict__ xin, const float* __restrict__ cb,
           float* __restrict__ dout, unsigned long long out_size) {
    extern __shared__ float sm[];
    float* X    = sm;                          // [256][64] residual, [d][t]
    float* E0   = X + DD * TILE;               // double-buffered [16][EPITCH] e chunks
    float* E1   = E0 + 16 * EPITCH;
    float* E2s  = E1 + 16 * EPITCH;            // [128] ||e||^2 of current code block
    float* SCRV = E2s + 128;                   // [64][16]
    int*   SCRI = (int*)(SCRV + TILE * 16);    // [64][16]
    float* RUNV = (float*)(SCRI + TILE * 16);  // [64]
    int*   RUNI = (int*)(RUNV + TILE);         // [64]
    float* Asm  = (float*)(RUNI + TILE);       // [64] ||x||^2 per token

    const int tid  = threadIdx.x;
    const int g    = blockIdx.y;
    const int tile = blockIdx.x;
    const int b    = tile >> 6;
    const int t0   = (tile & 63) << 6;
    const float* xb = xin + ((size_t)b * (GG * DD) + (size_t)g * DD) * TT + t0;

    for (int i = tid; i < DD * TILE; i += NTH) {
        int d = i >> 6, t = i & 63;
        X[i] = xb[(size_t)d * TT + t];
    }
    __syncthreads();

    const int tm = tid & 15;   // tokens 4*tm .. 4*tm+3
    const int tn = tid >> 4;   // codes  8*tn .. 8*tn+7 (4 f32x2 pairs)
    const int q  = tid & 3;    // d-quad for chunk loads
    const int kc = tid >> 2;   // code row for chunk loads (0..63)

    double lacc = 0.0;

    for (int l = 0; l < LL; ++l) {
        const float* cbl = cb + ((size_t)(l * GG + g)) * KK * DD;

        // a_n = sequential sum of fl(x^2), d ascending
        if (tid < TILE) {
            float s = 0.0f;
            const float* xc = X + tid;
#pragma unroll 8
            for (int d = 0; d < DD; ++d) {
                float v = xc[d * TILE];
                s = __fadd_rn(s, __fmul_rn(v, v));
            }
            Asm[tid] = s;
            RUNV[tid] = 3.0e38f; RUNI[tid] = 0;
        }
        __syncthreads();

        for (int kb = 0; kb < 8; ++kb) {               // 8 blocks of 128 codes
            const float* cblk = cbl + (size_t)kb * 128 * DD;
            if (tid < 128) E2s[tid] = g_e2[(l * GG + g) * KK + kb * 128 + tid];

            u64t acc[4][4];
#pragma unroll
            for (int i = 0; i < 4; ++i)
#pragma unroll
                for (int j = 0; j < 4; ++j) acc[i][j] = 0ull;

            // prefetch + stage chunk 0
            float4 nf0 = *(const float4*)(cblk + (size_t)kc * DD + q * 4);
            float4 nf1 = *(const float4*)(cblk + (size_t)(64 + kc) * DD + q * 4);
            {
                float* dst = E0;
                dst[(q * 4 + 0) * EPITCH + kc] = nf0.x;
                dst[(q * 4 + 1) * EPITCH + kc] = nf0.y;
                dst[(q * 4 + 2) * EPITCH + kc] = nf0.z;
                dst[(q * 4 + 3) * EPITCH + kc] = nf0.w;
                dst[(q * 4 + 0) * EPITCH + 64 + kc] = nf1.x;
                dst[(q * 4 + 1) * EPITCH + 64 + kc] = nf1.y;
                dst[(q * 4 + 2) * EPITCH + 64 + kc] = nf1.z;
                dst[(q * 4 + 3) * EPITCH + 64 + kc] = nf1.w;
            }
            __syncthreads();

#pragma unroll 1
            for (int dc = 0; dc < 16; ++dc) {          // 16 d-chunks of 16
                if (dc < 15) {
                    nf0 = *(const float4*)(cblk + (size_t)kc * DD + (dc + 1) * 16 + q * 4);
                    nf1 = *(const float4*)(cblk + (size_t)(64 + kc) * DD + (dc + 1) * 16 + q * 4);
                }
                const float* eb = (dc & 1) ? E1 : E0;
#pragma unroll
                for (int dd = 0; dd < 16; ++dd) {      // sequential d ascending
                    const float* xr = X + (dc * 16 + dd) * TILE + 4 * tm;
                    float4 a = *(const float4*)xr;
                    const float* er = eb + dd * EPITCH + 8 * tn;
                    ulonglong2 b01 = *(const ulonglong2*)er;
                    ulonglong2 b23 = *(const ulonglong2*)(er + 4);
                    u64t ap[4] = {dup2(a.x), dup2(a.y), dup2(a.z), dup2(a.w)};
                    u64t bp[4] = {b01.x, b01.y, b23.x, b23.y};
#pragma unroll
                    for (int i = 0; i < 4; ++i)
#pragma unroll
                        for (int j = 0; j < 4; ++j)
                            fma2(acc[i][j], ap[i], bp[j]);
                }
                if (dc < 15) {
                    float* dst = (dc & 1) ? E0 : E1;
                    dst[(q * 4 + 0) * EPITCH + kc] = nf0.x;
                    dst[(q * 4 + 1) * EPITCH + kc] = nf0.y;
                    dst[(q * 4 + 2) * EPITCH + kc] = nf0.z;
                    dst[(q * 4 + 3) * EPITCH + kc] = nf0.w;
                    dst[(q * 4 + 0) * EPITCH + 64 + kc] = nf1.x;
                    dst[(q * 4 + 1) * EPITCH + 64 + kc] = nf1.y;
                    dst[(q * 4 + 2) * EPITCH + 64 + kc] = nf1.z;
                    dst[(q * 4 + 3) * EPITCH + 64 + kc] = nf1.w;
                }
                __syncthreads();
            }

            // local argmin: d = fl( fl(a + b_k) - 2c ), ascending code order
#pragma unroll
            for (int i = 0; i < 4; ++i) {
                float a_tok = Asm[4 * tm + i];
                float best = 3.0e38f; int bi = 0;
#pragma unroll
                for (int jp = 0; jp < 4; ++jp) {
                    float clo, chi;
                    unpack2(acc[i][jp], clo, chi);
                    float t1 = __fadd_rn(a_tok, E2s[8 * tn + 2 * jp]);
                    float dv = __fadd_rn(t1, __fmul_rn(-2.0f, clo));
                    if (dv < best) { best = dv; bi = 2 * jp; }
                    t1 = __fadd_rn(a_tok, E2s[8 * tn + 2 * jp + 1]);
                    dv = __fadd_rn(t1, __fmul_rn(-2.0f, chi));
                    if (dv < best) { best = dv; bi = 2 * jp + 1; }
                }
                SCRV[(4 * tm + i) * 16 + tn] = best;
                SCRI[(4 * tm + i) * 16 + tn] = kb * 128 + 8 * tn + bi;
            }
            __syncthreads();
            if (tid < TILE) {                           // merge, first-index wins
                float bv = RUNV[tid]; int bi = RUNI[tid];
#pragma unroll
                for (int t16 = 0; t16 < 16; ++t16) {
                    float v = SCRV[tid * 16 + t16];
                    if (v < bv) { bv = v; bi = SCRI[tid * 16 + t16]; }
                }
                RUNV[tid] = bv; RUNI[tid] = bi;
            }
            __syncthreads();
        }

        // indices out
        if (tid < TILE && out_size > IDX_OFF) {
            size_t n = (size_t)b * TT + t0 + tid;
            size_t o = IDX_OFF + ((size_t)(l * GG + g)) * NTOK + n;
            if (o < out_size) dout[o] = (float)RUNI[tid];
        }

        // residual update (reference STE elementwise):
        {
            int token = tid >> 2, dq = tid & 3;
            int code  = RUNI[token];
            const float* ev = cbl + (size_t)code * DD + dq * 64;
            float* xc = X + (dq * 64) * TILE + token;
#pragma unroll 8
            for (int dd = 0; dd < 64; ++dd) {
                float x  = xc[dd * TILE];
                float dl = __fsub_rn(ev[dd], x);
                float qn = __fadd_rn(x, dl);
                xc[dd * TILE] = __fsub_rn(x, qn);
                lacc += (double)dl * (double)dl;
            }
        }
        __syncthreads();
    }

    // quantized_out = xin - final residual
    for (int i = tid; i < DD * TILE; i += NTH) {
        int d = i >> 6, t = i & 63;
        size_t o = ((size_t)b * (GG * DD) + (size_t)g * DD + d) * TT + t0 + t;
        if (o < out_size && o < QOUT_ELEMS)
            dout[o] = __fsub_rn(xb[(size_t)d * TT + t], X[i]);
    }

    // deterministic per-CTA loss partial
    double* red = (double*)SCRV;
    red[tid] = lacc;
    __syncthreads();
    for (int s = 128; s > 0; s >>= 1) {
        if (tid < s) red[tid] += red[tid + s];
        __syncthreads();
    }
    if (tid == 0) g_loss[blockIdx.y * 1024 + blockIdx.x] = red[0];
}

// ---------------------------------------------------------------- loss reduce
__global__ void loss_kernel(float* __restrict__ dout, unsigned long long out_size) {
    __shared__ double red[256];
    int tid = threadIdx.x;
    double s = 0.0;
    for (int i = tid; i < 2048; i += 256) s += g_loss[i];
    red[tid] = s;
    __syncthreads();
    for (int st = 128; st > 0; st >>= 1) {
        if (tid < st) red[tid] += red[tid + st];
        __syncthreads();
    }
    if (tid == 0 && out_size > LOSS_OFF)
        dout[LOSS_OFF] = (float)(1.25 * red[0] / (8.0 * 33554432.0));
}

// ---------------------------------------------------------------- launch
extern "C" void kernel_launch(void* const* d_in, const int* in_sizes, int n_in,
                              void* d_out, int out_size) {
    const float* xin = (const float*)d_in[0];
    const float* cb  = (const float*)d_in[1];
    if (n_in >= 2 && in_sizes[0] == LL * GG * KK * DD) {
        xin = (const float*)d_in[1];
        cb  = (const float*)d_in[0];
    }
    float* dout = (float*)d_out;
    unsigned long long osz = (unsigned long long)out_size;

    static bool attr_set = false;
    size_t smem = (size_t)(DD * TILE + 32 * EPITCH + 128 + TILE * 16 * 2 + TILE * 3) * 4;
    if (!attr_set) {
        cudaFuncSetAttribute(rvq_kernel, cudaFuncAttributeMaxDynamicSharedMemorySize, (int)smem);
        attr_set = true;
    }

    e2_kernel<<<(LL * GG * KK + 255) / 256, 256>>>(cb);
    dim3 grid(1024, GG);
    rvq_kernel<<<grid, NTH, smem>>>(xin, cb, dout, osz);
    loss_kernel<<<1, 256>>>(dout, osz);
}